// round 16
// baseline (speedup 1.0000x reference)
#include <cuda_runtime.h>
#include <cuda_fp16.h>
#include <math.h>
#include <stdint.h>

#define D 128
#define MAXN 100000
#define MAXE 1600000

// ---------------- device scratch ----------------
__device__ __half g_qh[MAXN * D];
__device__ __half g_kvh[MAXN * 2 * D];  // interleaved: per node, per 4-dim chunk: {k[4],v[4]}
__device__ __half g_th[MAXN * D];       // inter-layer tangent (exp/log cancels)
__device__ int    g_cnt[MAXN];
__device__ int    g_off[MAXN + 1];
__device__ int    g_cur[MAXN];
__device__ int    g_esrc[MAXE];
__device__ int    g_bsum[128];
__device__ int    g_btop[128];

// ---------------- helpers ----------------
__device__ __forceinline__ uint32_t smem_u32(const void* p) {
    uint32_t a;
    asm("{ .reg .u64 t; cvta.to.shared.u64 t, %1; cvt.u32.u64 %0, t; }"
        : "=r"(a) : "l"(p));
    return a;
}
__device__ __forceinline__ unsigned pk16(float a, float b) {
    __half2 h = __floats2half2_rn(a, b);
    return *reinterpret_cast<unsigned*>(&h);
}
__device__ __forceinline__ float wredsum(float v) {
    #pragma unroll
    for (int o = 16; o; o >>= 1) v += __shfl_xor_sync(0xffffffffu, v, o);
    return v;
}
__device__ __forceinline__ float4 h4f(uint2 u) {
    float2 fa = __half22float2(*reinterpret_cast<__half2*>(&u.x));
    float2 fb = __half22float2(*reinterpret_cast<__half2*>(&u.y));
    return make_float4(fa.x, fa.y, fb.x, fb.y);
}
__device__ __forceinline__ void ldsm_x4(uint32_t* r, uint32_t addr) {
    asm volatile("ldmatrix.sync.aligned.m8n8.x4.shared.b16 {%0,%1,%2,%3}, [%4];"
                 : "=r"(r[0]), "=r"(r[1]), "=r"(r[2]), "=r"(r[3]) : "r"(addr));
}
__device__ __forceinline__ void mma16816(float* d, const uint32_t* a,
                                         uint32_t b0, uint32_t b1) {
    asm volatile(
        "mma.sync.aligned.m16n8k16.row.col.f32.f16.f16.f32 "
        "{%0,%1,%2,%3}, {%4,%5,%6,%7}, {%8,%9}, {%0,%1,%2,%3};"
        : "+f"(d[0]), "+f"(d[1]), "+f"(d[2]), "+f"(d[3])
        : "r"(a[0]), "r"(a[1]), "r"(a[2]), "r"(a[3]), "r"(b0), "r"(b1));
}

// ---------------- CSR build ----------------
__global__ void hist_kernel(const int* __restrict__ dst, int E) {
    int i = blockIdx.x * blockDim.x + threadIdx.x;
    if (i < E) atomicAdd(&g_cnt[dst[i]], 1);
}
__global__ void scan_local(int N) {
    __shared__ int sh[256];
    int b = blockIdx.x, t = threadIdx.x;
    int i0 = b * 1024 + t * 4;
    int c0 = (i0 + 0 < N) ? g_cnt[i0 + 0] : 0;
    int c1 = (i0 + 1 < N) ? g_cnt[i0 + 1] : 0;
    int c2 = (i0 + 2 < N) ? g_cnt[i0 + 2] : 0;
    int c3 = (i0 + 3 < N) ? g_cnt[i0 + 3] : 0;
    int s = c0 + c1 + c2 + c3;
    sh[t] = s;
    __syncthreads();
    for (int o = 1; o < 256; o <<= 1) {
        int v = (t >= o) ? sh[t - o] : 0;
        __syncthreads();
        sh[t] += v;
        __syncthreads();
    }
    int ex = sh[t] - s;
    if (i0 + 0 < N) g_off[i0 + 0] = ex; ex += c0;
    if (i0 + 1 < N) g_off[i0 + 1] = ex; ex += c1;
    if (i0 + 2 < N) g_off[i0 + 2] = ex; ex += c2;
    if (i0 + 3 < N) g_off[i0 + 3] = ex;
    if (t == 255) g_bsum[b] = sh[255];
}
__global__ void scan_tops(int nb) {
    __shared__ int sh[128];
    int t = threadIdx.x;
    int v = (t < nb) ? g_bsum[t] : 0;
    sh[t] = v;
    __syncthreads();
    for (int o = 1; o < 128; o <<= 1) {
        int u = (t >= o) ? sh[t - o] : 0;
        __syncthreads();
        sh[t] += u;
        __syncthreads();
    }
    g_btop[t] = sh[t] - v;
}
__global__ void scan_add(int N, int E) {
    int i = blockIdx.x * blockDim.x + threadIdx.x;
    if (i < N) {
        int o = g_off[i] + g_btop[i >> 10];
        g_off[i] = o;
        g_cur[i] = o;
    }
    if (i == 0) g_off[N] = E;
}
__global__ void scatter_kernel(const int* __restrict__ src,
                               const int* __restrict__ dst, int E) {
    int i = blockIdx.x * blockDim.x + threadIdx.x;
    if (i < E) {
        int p = atomicAdd(&g_cur[dst[i]], 1);
        g_esrc[p] = src[i];
    }
}

// ---------------- fused log_map + q/k/v GEMM (fp16 HMMA; R11 form) ----------------
#define AH_OFF   0
#define WQ_OFF   16384
#define WK_OFF   49152
#define WVH_OFF  81920
#define GEMM_SMEM 115712

__device__ __forceinline__ void gemm_pass32_qk(float (*aq)[4], float (*ak)[4],
                                               uint32_t Ap, uint32_t Bq,
                                               uint32_t Bk, int lane, int R0,
                                               int C0) {
    int arow = R0 + (lane & 15);
    int brl = lane & 15;
    int chi = lane >> 4;
    uint32_t abase = Ap + arow * 256;
    int asw = arow & 7;
    #pragma unroll
    for (int kk = 0; kk < 8; kk++) {
        int cidx = kk * 2 + chi;
        uint32_t a[4];
        ldsm_x4(a, abase + (uint32_t)((cidx ^ asw) << 4));
        #pragma unroll
        for (int nb2 = 0; nb2 < 2; nb2++) {
            int brow = C0 + nb2 * 16 + brl;
            uint32_t boff = brow * 256 + (uint32_t)((cidx ^ (brow & 7)) << 4);
            uint32_t b[4];
            ldsm_x4(b, Bq + boff);
            mma16816(aq[nb2 * 2 + 0], a, b[0], b[2]);
            mma16816(aq[nb2 * 2 + 1], a, b[1], b[3]);
            ldsm_x4(b, Bk + boff);
            mma16816(ak[nb2 * 2 + 0], a, b[0], b[2]);
            mma16816(ak[nb2 * 2 + 1], a, b[1], b[3]);
        }
    }
}

__device__ __forceinline__ void gemm_pass32(float (*acc)[4], uint32_t Ap,
                                            uint32_t Bp, int lane, int R0,
                                            int C0) {
    int arow = R0 + (lane & 15);
    int brl = lane & 15;
    int chi = lane >> 4;
    uint32_t abase = Ap + arow * 256;
    int asw = arow & 7;
    #pragma unroll
    for (int kk = 0; kk < 8; kk++) {
        int cidx = kk * 2 + chi;
        uint32_t a[4];
        ldsm_x4(a, abase + (uint32_t)((cidx ^ asw) << 4));
        #pragma unroll
        for (int nb2 = 0; nb2 < 2; nb2++) {
            int brow = C0 + nb2 * 16 + brl;
            uint32_t b[4];
            ldsm_x4(b, Bp + brow * 256 + (uint32_t)((cidx ^ (brow & 7)) << 4));
            mma16816(acc[nb2 * 2 + 0], a, b[0], b[2]);
            mma16816(acc[nb2 * 2 + 1], a, b[1], b[3]);
        }
    }
}

// q: plain row-major fp16
__device__ __forceinline__ void store32_q(float (*acc)[4],
                                          const float* __restrict__ bias,
                                          int lane, int R0, int C0, int row0,
                                          int N) {
    int g = lane >> 2, t = lane & 3;
    int r0g = row0 + R0 + g;
    int r1g = r0g + 8;
    #pragma unroll
    for (int nb = 0; nb < 4; nb++) {
        int col = C0 + nb * 8 + 2 * t;
        float b0 = __ldg(&bias[col]), b1 = __ldg(&bias[col + 1]);
        if (r0g < N)
            *(__half2*)(g_qh + r0g * 128 + col) =
                __floats2half2_rn(acc[nb][0] + b0, acc[nb][1] + b1);
        if (r1g < N)
            *(__half2*)(g_qh + r1g * 128 + col) =
                __floats2half2_rn(acc[nb][2] + b0, acc[nb][3] + b1);
    }
}

// k/v: interleaved per 4-dim chunk: addr = row*256 + (col/4)*8 + (col&3) + sel
// sel = 0 for k, 4 for v. col is even so the half2 stays inside the 4-half chunk.
__device__ __forceinline__ void store32_kv(float (*acc)[4], int sel,
                                           const float* __restrict__ bias,
                                           int lane, int R0, int C0, int row0,
                                           int N) {
    int g = lane >> 2, t = lane & 3;
    int r0g = row0 + R0 + g;
    int r1g = r0g + 8;
    #pragma unroll
    for (int nb = 0; nb < 4; nb++) {
        int col = C0 + nb * 8 + 2 * t;
        int ioff = ((col >> 2) << 3) + (col & 3) + sel;
        float b0 = __ldg(&bias[col]), b1 = __ldg(&bias[col + 1]);
        if (r0g < N)
            *(__half2*)(g_kvh + r0g * 256 + ioff) =
                __floats2half2_rn(acc[nb][0] + b0, acc[nb][1] + b1);
        if (r1g < N)
            *(__half2*)(g_kvh + r1g * 256 + ioff) =
                __floats2half2_rn(acc[nb][2] + b0, acc[nb][3] + b1);
    }
}

// xin: fp32 embeddings (layer 0, log_map fused) OR tin: fp16 tangent (layer>=1)
__global__ void __launch_bounds__(512, 2)
qkv_gemm_hmma(const float* __restrict__ xin, const __half* __restrict__ tin,
              const float* __restrict__ Wq, const float* __restrict__ bq,
              const float* __restrict__ Wk, const float* __restrict__ bk,
              const float* __restrict__ Wv, const float* __restrict__ bv,
              const float* __restrict__ curv, int N, int numTiles) {
    extern __shared__ char dsm[];
    char* SB = (char*)((((uintptr_t)dsm) + 1023) & ~(uintptr_t)1023);
    uint32_t sb = smem_u32(SB);

    int tid = threadIdx.x;
    int lane = tid & 31;
    int wid = tid >> 5;   // 0..15

    for (int it = 0; it < 8; it++) {
        int c = wid * 8 + it;
        float4 wq = ((const float4*)Wq)[c * 32 + lane];
        float4 wk = ((const float4*)Wk)[c * 32 + lane];
        float4 wv = ((const float4*)Wv)[c * 32 + lane];
        uint32_t off = (uint32_t)(c * 256 + (((lane >> 1) ^ (c & 7)) << 4) +
                                  (lane & 1) * 8);
        *(uint2*)(SB + WQ_OFF + off) = make_uint2(pk16(wq.x, wq.y), pk16(wq.z, wq.w));
        *(uint2*)(SB + WK_OFF + off) = make_uint2(pk16(wk.x, wk.y), pk16(wk.z, wk.w));
        *(uint2*)(SB + WVH_OFF + off) = make_uint2(pk16(wv.x, wv.y), pk16(wv.z, wv.w));
    }
    __syncthreads();

    float sc = sqrtf(curv[0]);
    float inv_sc2 = 2.0f / sc;
    int R0 = (wid >> 2) * 16;
    int C0 = (wid & 3) * 32;

    for (int tile = blockIdx.x; tile < numTiles; tile += gridDim.x) {
        int row0 = tile * 64;
        if (tin) {
            for (int it = 0; it < 4; it++) {
                int m = wid * 4 + it;
                int grow = row0 + m;
                uint2 hv = (grow < N) ? __ldg(&((const uint2*)tin)[grow * 32 + lane])
                                      : make_uint2(0u, 0u);
                uint32_t off = (uint32_t)(m * 256 + (((lane >> 1) ^ (m & 7)) << 4) +
                                          (lane & 1) * 8);
                *(uint2*)(SB + AH_OFF + off) = hv;
            }
        } else {
            for (int it = 0; it < 4; it++) {
                int m = wid * 4 + it;
                int grow = row0 + m;
                float4 xv = (grow < N) ? ((const float4*)xin)[grow * 32 + lane]
                                       : make_float4(0.f, 0.f, 0.f, 0.f);
                float n2 = wredsum(xv.x * xv.x + xv.y * xv.y + xv.z * xv.z + xv.w * xv.w);
                float nrm = sqrtf(n2);
                float f = (nrm > 1e-30f) ? inv_sc2 * atanhf(sc * nrm) / nrm : 2.0f;
                uint32_t off = (uint32_t)(m * 256 + (((lane >> 1) ^ (m & 7)) << 4) +
                                          (lane & 1) * 8);
                *(uint2*)(SB + AH_OFF + off) =
                    make_uint2(pk16(f * xv.x, f * xv.y), pk16(f * xv.z, f * xv.w));
            }
        }
        __syncthreads();

        float aq[4][4], ak[4][4];
        #pragma unroll
        for (int i = 0; i < 4; i++)
            #pragma unroll
            for (int j = 0; j < 4; j++) { aq[i][j] = 0.f; ak[i][j] = 0.f; }
        gemm_pass32_qk(aq, ak, sb + AH_OFF, sb + WQ_OFF, sb + WK_OFF,
                       lane, R0, C0);
        store32_q(aq, bq, lane, R0, C0, row0, N);
        store32_kv(ak, 0, bk, lane, R0, C0, row0, N);

        #pragma unroll
        for (int i = 0; i < 4; i++)
            #pragma unroll
            for (int j = 0; j < 4; j++) aq[i][j] = 0.f;
        gemm_pass32(aq, sb + AH_OFF, sb + WVH_OFF, lane, R0, C0);
        store32_kv(aq, 4, bv, lane, R0, C0, row0, N);

        __syncthreads();
    }
}

// ---------------- attention (1 node/warp, 4-edge unroll, fused kv gather) ----------------
// mode 0: write tangent h fp16 to g_th; mode 1: exp_map -> fp32 out
__global__ void __launch_bounds__(256)
edge_kernel(const float* __restrict__ curv, float* __restrict__ out, int N,
            int mode) {
    int lane = threadIdx.x & 31;
    int node = blockIdx.x * 8 + (threadIdx.x >> 5);
    if (node >= N) return;

    const uint2* qp = (const uint2*)g_qh;
    float4 qr = h4f(__ldg(&qp[node * 32 + lane]));
    int e0 = g_off[node];
    int e1 = g_off[node + 1];
    const float scale = 0.08838834764831845f;  // 1/sqrt(128)
    const uint4* kvp = (const uint4*)g_kvh;    // 32 chunks of 16B per node

    float z = 0.f;
    float4 acc = make_float4(0.f, 0.f, 0.f, 0.f);

    int e = e0;
    for (; e + 4 <= e1; e += 4) {
        int s0 = __ldg(&g_esrc[e]);
        int s1 = __ldg(&g_esrc[e + 1]);
        int s2 = __ldg(&g_esrc[e + 2]);
        int s3 = __ldg(&g_esrc[e + 3]);
        // one 16B gather per edge: {k[4lane..+3], v[4lane..+3]}
        uint4 kv0 = __ldg(&kvp[s0 * 32 + lane]);
        uint4 kv1 = __ldg(&kvp[s1 * 32 + lane]);
        uint4 kv2 = __ldg(&kvp[s2 * 32 + lane]);
        uint4 kv3 = __ldg(&kvp[s3 * 32 + lane]);
        float4 k0 = h4f(make_uint2(kv0.x, kv0.y));
        float4 k1 = h4f(make_uint2(kv1.x, kv1.y));
        float4 k2 = h4f(make_uint2(kv2.x, kv2.y));
        float4 k3 = h4f(make_uint2(kv3.x, kv3.y));
        float d0 = qr.x * k0.x + qr.y * k0.y + qr.z * k0.z + qr.w * k0.w;
        float d1 = qr.x * k1.x + qr.y * k1.y + qr.z * k1.z + qr.w * k1.w;
        float d2 = qr.x * k2.x + qr.y * k2.y + qr.z * k2.z + qr.w * k2.w;
        float d3 = qr.x * k3.x + qr.y * k3.y + qr.z * k3.z + qr.w * k3.w;
        #pragma unroll
        for (int o = 16; o; o >>= 1) {
            d0 += __shfl_xor_sync(0xffffffffu, d0, o);
            d1 += __shfl_xor_sync(0xffffffffu, d1, o);
            d2 += __shfl_xor_sync(0xffffffffu, d2, o);
            d3 += __shfl_xor_sync(0xffffffffu, d3, o);
        }
        float p0 = __expf(d0 * scale);
        float p1 = __expf(d1 * scale);
        float p2 = __expf(d2 * scale);
        float p3 = __expf(d3 * scale);
        z += (p0 + p1) + (p2 + p3);
        float4 v0 = h4f(make_uint2(kv0.z, kv0.w));
        float4 v1 = h4f(make_uint2(kv1.z, kv1.w));
        float4 v2 = h4f(make_uint2(kv2.z, kv2.w));
        float4 v3 = h4f(make_uint2(kv3.z, kv3.w));
        acc.x += p0 * v0.x + p1 * v1.x + p2 * v2.x + p3 * v3.x;
        acc.y += p0 * v0.y + p1 * v1.y + p2 * v2.y + p3 * v3.y;
        acc.z += p0 * v0.z + p1 * v1.z + p2 * v2.z + p3 * v3.z;
        acc.w += p0 * v0.w + p1 * v1.w + p2 * v2.w + p3 * v3.w;
    }
    for (; e < e1; e++) {
        int s0 = __ldg(&g_esrc[e]);
        uint4 kv0 = __ldg(&kvp[s0 * 32 + lane]);
        float4 k0 = h4f(make_uint2(kv0.x, kv0.y));
        float4 v0 = h4f(make_uint2(kv0.z, kv0.w));
        float d0 = qr.x * k0.x + qr.y * k0.y + qr.z * k0.z + qr.w * k0.w;
        d0 = wredsum(d0);
        float p0 = __expf(d0 * scale);
        z += p0;
        acc.x += p0 * v0.x;
        acc.y += p0 * v0.y;
        acc.z += p0 * v0.z;
        acc.w += p0 * v0.w;
    }

    float inv = 1.0f / z;
    float4 h = make_float4(acc.x * inv, acc.y * inv, acc.z * inv, acc.w * inv);

    if (mode == 0) {
        ((uint2*)g_th)[node * 32 + lane] =
            make_uint2(pk16(h.x, h.y), pk16(h.z, h.w));
        return;
    }
    float n2 = wredsum(h.x * h.x + h.y * h.y + h.z * h.z + h.w * h.w);
    float nrm = sqrtf(n2);
    float sc = sqrtf(curv[0]);
    float f = (nrm > 1e-30f) ? tanhf(0.5f * sc * nrm) / (sc * nrm) : 0.5f;
    ((float4*)out)[node * 32 + lane] =
        make_float4(f * h.x, f * h.y, f * h.z, f * h.w);
}

// ---------------- launch ----------------
extern "C" void kernel_launch(void* const* d_in, const int* in_sizes, int n_in,
                              void* d_out, int out_size) {
    const float* emb  = (const float*)d_in[0];
    const float* Wq   = (const float*)d_in[1];
    const float* bq   = (const float*)d_in[2];
    const float* Wk   = (const float*)d_in[3];
    const float* bk   = (const float*)d_in[4];
    const float* Wv   = (const float*)d_in[5];
    const float* bv   = (const float*)d_in[6];
    const float* curv = (const float*)d_in[7];
    const int*   src  = (const int*)d_in[8];
    const int*   dst  = (const int*)d_in[9];

    int N = in_sizes[0] / D;
    int E = in_sizes[8];
    int L = in_sizes[1] / (D * D);

    cudaFuncSetAttribute(qkv_gemm_hmma,
                         cudaFuncAttributeMaxDynamicSharedMemorySize, GEMM_SMEM);

    void* p;
    cudaGetSymbolAddress(&p, g_th);
    const __half* gth = (const __half*)p;
    cudaGetSymbolAddress(&p, g_cnt);
    void* gcnt_v = p;

    int nb = (N + 1023) >> 10;
    int numTiles = (N + 63) / 64;
    int nodeBlocks = (N + 7) / 8;

    cudaStream_t s2;
    cudaStreamCreateWithFlags(&s2, cudaStreamNonBlocking);
    cudaEvent_t evF, evJ;
    cudaEventCreateWithFlags(&evF, cudaEventDisableTiming);
    cudaEventCreateWithFlags(&evJ, cudaEventDisableTiming);

    cudaMemsetAsync(gcnt_v, 0, (size_t)N * sizeof(int));

    // fork: GEMM layer 0 on s2 concurrent with CSR chain on main stream
    cudaEventRecord(evF, 0);
    cudaStreamWaitEvent(s2, evF, 0);
    qkv_gemm_hmma<<<296, 512, GEMM_SMEM, s2>>>(emb, nullptr,
                                               Wq, bq, Wk, bk, Wv, bv,
                                               curv, N, numTiles);
    cudaEventRecord(evJ, s2);

    hist_kernel<<<(E + 255) / 256, 256>>>(dst, E);
    scan_local<<<nb, 256>>>(N);
    scan_tops<<<1, 128>>>(nb);
    scan_add<<<(N + 255) / 256, 256>>>(N, E);
    scatter_kernel<<<(E + 255) / 256, 256>>>(src, dst, E);

    cudaStreamWaitEvent(0, evJ, 0);

    edge_kernel<<<nodeBlocks, 256>>>(curv, (float*)d_out, N, (L == 1) ? 1 : 0);
    for (int l = 1; l < L; l++) {
        qkv_gemm_hmma<<<296, 512, GEMM_SMEM>>>(nullptr, gth,
                                               Wq + l * D * D, bq + l * D,
                                               Wk + l * D * D, bk + l * D,
                                               Wv + l * D * D, bv + l * D,
                                               curv, N, numTiles);
        edge_kernel<<<nodeBlocks, 256>>>(curv, (float*)d_out, N,
                                         (l == L - 1) ? 1 : 0);
    }

    cudaEventDestroy(evF);
    cudaEventDestroy(evJ);
    cudaStreamDestroy(s2);
}

// round 17
// speedup vs baseline: 1.0542x; 1.0542x over previous
#include <cuda_runtime.h>
#include <cuda_fp16.h>
#include <math.h>
#include <stdint.h>

#define D 128
#define MAXN 100000
#define MAXE 1600000

// ---------------- device scratch ----------------
__device__ __half g_qh[MAXN * D];
__device__ __half g_kh[MAXN * D];
__device__ __half g_vh[MAXN * D];
__device__ __half g_th[MAXN * D];   // inter-layer tangent (exp/log cancels)
__device__ int    g_cnt[MAXN];
__device__ int    g_off[MAXN + 1];
__device__ int    g_cur[MAXN];
__device__ int    g_esrc[MAXE];
__device__ int    g_bsum[128];
__device__ int    g_btop[128];

// ---------------- helpers ----------------
__device__ __forceinline__ uint32_t smem_u32(const void* p) {
    uint32_t a;
    asm("{ .reg .u64 t; cvta.to.shared.u64 t, %1; cvt.u32.u64 %0, t; }"
        : "=r"(a) : "l"(p));
    return a;
}
__device__ __forceinline__ unsigned pk16(float a, float b) {
    __half2 h = __floats2half2_rn(a, b);
    return *reinterpret_cast<unsigned*>(&h);
}
__device__ __forceinline__ float wredsum(float v) {
    #pragma unroll
    for (int o = 16; o; o >>= 1) v += __shfl_xor_sync(0xffffffffu, v, o);
    return v;
}
__device__ __forceinline__ float4 h4f(uint2 u) {
    float2 fa = __half22float2(*reinterpret_cast<__half2*>(&u.x));
    float2 fb = __half22float2(*reinterpret_cast<__half2*>(&u.y));
    return make_float4(fa.x, fa.y, fb.x, fb.y);
}
__device__ __forceinline__ void ldsm_x4(uint32_t* r, uint32_t addr) {
    asm volatile("ldmatrix.sync.aligned.m8n8.x4.shared.b16 {%0,%1,%2,%3}, [%4];"
                 : "=r"(r[0]), "=r"(r[1]), "=r"(r[2]), "=r"(r[3]) : "r"(addr));
}
__device__ __forceinline__ void mma16816(float* d, const uint32_t* a,
                                         uint32_t b0, uint32_t b1) {
    asm volatile(
        "mma.sync.aligned.m16n8k16.row.col.f32.f16.f16.f32 "
        "{%0,%1,%2,%3}, {%4,%5,%6,%7}, {%8,%9}, {%0,%1,%2,%3};"
        : "+f"(d[0]), "+f"(d[1]), "+f"(d[2]), "+f"(d[3])
        : "r"(a[0]), "r"(a[1]), "r"(a[2]), "r"(a[3]), "r"(b0), "r"(b1));
}

// ---------------- CSR build ----------------
__global__ void hist_kernel(const int* __restrict__ dst, int E) {
    int i = blockIdx.x * blockDim.x + threadIdx.x;
    if (i < E) atomicAdd(&g_cnt[dst[i]], 1);
}
__global__ void scan_local(int N) {
    __shared__ int sh[256];
    int b = blockIdx.x, t = threadIdx.x;
    int i0 = b * 1024 + t * 4;
    int c0 = (i0 + 0 < N) ? g_cnt[i0 + 0] : 0;
    int c1 = (i0 + 1 < N) ? g_cnt[i0 + 1] : 0;
    int c2 = (i0 + 2 < N) ? g_cnt[i0 + 2] : 0;
    int c3 = (i0 + 3 < N) ? g_cnt[i0 + 3] : 0;
    int s = c0 + c1 + c2 + c3;
    sh[t] = s;
    __syncthreads();
    for (int o = 1; o < 256; o <<= 1) {
        int v = (t >= o) ? sh[t - o] : 0;
        __syncthreads();
        sh[t] += v;
        __syncthreads();
    }
    int ex = sh[t] - s;
    if (i0 + 0 < N) g_off[i0 + 0] = ex; ex += c0;
    if (i0 + 1 < N) g_off[i0 + 1] = ex; ex += c1;
    if (i0 + 2 < N) g_off[i0 + 2] = ex; ex += c2;
    if (i0 + 3 < N) g_off[i0 + 3] = ex;
    if (t == 255) g_bsum[b] = sh[255];
}
__global__ void scan_tops(int nb) {
    __shared__ int sh[128];
    int t = threadIdx.x;
    int v = (t < nb) ? g_bsum[t] : 0;
    sh[t] = v;
    __syncthreads();
    for (int o = 1; o < 128; o <<= 1) {
        int u = (t >= o) ? sh[t - o] : 0;
        __syncthreads();
        sh[t] += u;
        __syncthreads();
    }
    g_btop[t] = sh[t] - v;
}
__global__ void scan_add(int N, int E) {
    int i = blockIdx.x * blockDim.x + threadIdx.x;
    if (i < N) {
        int o = g_off[i] + g_btop[i >> 10];
        g_off[i] = o;
        g_cur[i] = o;
    }
    if (i == 0) g_off[N] = E;
}
__global__ void scatter_kernel(const int* __restrict__ src,
                               const int* __restrict__ dst, int E) {
    int i = blockIdx.x * blockDim.x + threadIdx.x;
    if (i < E) {
        int p = atomicAdd(&g_cur[dst[i]], 1);
        g_esrc[p] = src[i];
    }
}

// ---------------- fused log_map + q/k/v GEMM (fp16 HMMA; R11 form) ----------------
#define AH_OFF   0
#define WQ_OFF   16384
#define WK_OFF   49152
#define WVH_OFF  81920
#define GEMM_SMEM 115712

__device__ __forceinline__ void gemm_pass32_qk(float (*aq)[4], float (*ak)[4],
                                               uint32_t Ap, uint32_t Bq,
                                               uint32_t Bk, int lane, int R0,
                                               int C0) {
    int arow = R0 + (lane & 15);
    int brl = lane & 15;
    int chi = lane >> 4;
    uint32_t abase = Ap + arow * 256;
    int asw = arow & 7;
    #pragma unroll
    for (int kk = 0; kk < 8; kk++) {
        int cidx = kk * 2 + chi;
        uint32_t a[4];
        ldsm_x4(a, abase + (uint32_t)((cidx ^ asw) << 4));
        #pragma unroll
        for (int nb2 = 0; nb2 < 2; nb2++) {
            int brow = C0 + nb2 * 16 + brl;
            uint32_t boff = brow * 256 + (uint32_t)((cidx ^ (brow & 7)) << 4);
            uint32_t b[4];
            ldsm_x4(b, Bq + boff);
            mma16816(aq[nb2 * 2 + 0], a, b[0], b[2]);
            mma16816(aq[nb2 * 2 + 1], a, b[1], b[3]);
            ldsm_x4(b, Bk + boff);
            mma16816(ak[nb2 * 2 + 0], a, b[0], b[2]);
            mma16816(ak[nb2 * 2 + 1], a, b[1], b[3]);
        }
    }
}

__device__ __forceinline__ void gemm_pass32(float (*acc)[4], uint32_t Ap,
                                            uint32_t Bp, int lane, int R0,
                                            int C0) {
    int arow = R0 + (lane & 15);
    int brl = lane & 15;
    int chi = lane >> 4;
    uint32_t abase = Ap + arow * 256;
    int asw = arow & 7;
    #pragma unroll
    for (int kk = 0; kk < 8; kk++) {
        int cidx = kk * 2 + chi;
        uint32_t a[4];
        ldsm_x4(a, abase + (uint32_t)((cidx ^ asw) << 4));
        #pragma unroll
        for (int nb2 = 0; nb2 < 2; nb2++) {
            int brow = C0 + nb2 * 16 + brl;
            uint32_t b[4];
            ldsm_x4(b, Bp + brow * 256 + (uint32_t)((cidx ^ (brow & 7)) << 4));
            mma16816(acc[nb2 * 2 + 0], a, b[0], b[2]);
            mma16816(acc[nb2 * 2 + 1], a, b[1], b[3]);
        }
    }
}

__device__ __forceinline__ void store32_h(float (*acc)[4], __half* out,
                                          const float* __restrict__ bias,
                                          int lane, int R0, int C0, int row0,
                                          int N) {
    int g = lane >> 2, t = lane & 3;
    int r0g = row0 + R0 + g;
    int r1g = r0g + 8;
    #pragma unroll
    for (int nb = 0; nb < 4; nb++) {
        int col = C0 + nb * 8 + 2 * t;
        float b0 = __ldg(&bias[col]), b1 = __ldg(&bias[col + 1]);
        if (r0g < N)
            *(__half2*)(out + r0g * 128 + col) =
                __floats2half2_rn(acc[nb][0] + b0, acc[nb][1] + b1);
        if (r1g < N)
            *(__half2*)(out + r1g * 128 + col) =
                __floats2half2_rn(acc[nb][2] + b0, acc[nb][3] + b1);
    }
}

// xin: fp32 embeddings (layer 0, log_map fused) OR tin: fp16 tangent (layer>=1)
__global__ void __launch_bounds__(512, 2)
qkv_gemm_hmma(const float* __restrict__ xin, const __half* __restrict__ tin,
              const float* __restrict__ Wq, const float* __restrict__ bq,
              const float* __restrict__ Wk, const float* __restrict__ bk,
              const float* __restrict__ Wv, const float* __restrict__ bv,
              const float* __restrict__ curv, int N, int numTiles) {
    extern __shared__ char dsm[];
    char* SB = (char*)((((uintptr_t)dsm) + 1023) & ~(uintptr_t)1023);
    uint32_t sb = smem_u32(SB);

    int tid = threadIdx.x;
    int lane = tid & 31;
    int wid = tid >> 5;   // 0..15

    for (int it = 0; it < 8; it++) {
        int c = wid * 8 + it;
        float4 wq = ((const float4*)Wq)[c * 32 + lane];
        float4 wk = ((const float4*)Wk)[c * 32 + lane];
        float4 wv = ((const float4*)Wv)[c * 32 + lane];
        uint32_t off = (uint32_t)(c * 256 + (((lane >> 1) ^ (c & 7)) << 4) +
                                  (lane & 1) * 8);
        *(uint2*)(SB + WQ_OFF + off) = make_uint2(pk16(wq.x, wq.y), pk16(wq.z, wq.w));
        *(uint2*)(SB + WK_OFF + off) = make_uint2(pk16(wk.x, wk.y), pk16(wk.z, wk.w));
        *(uint2*)(SB + WVH_OFF + off) = make_uint2(pk16(wv.x, wv.y), pk16(wv.z, wv.w));
    }
    __syncthreads();

    float sc = sqrtf(curv[0]);
    float inv_sc2 = 2.0f / sc;
    int R0 = (wid >> 2) * 16;
    int C0 = (wid & 3) * 32;

    for (int tile = blockIdx.x; tile < numTiles; tile += gridDim.x) {
        int row0 = tile * 64;
        if (tin) {
            for (int it = 0; it < 4; it++) {
                int m = wid * 4 + it;
                int grow = row0 + m;
                uint2 hv = (grow < N) ? __ldg(&((const uint2*)tin)[grow * 32 + lane])
                                      : make_uint2(0u, 0u);
                uint32_t off = (uint32_t)(m * 256 + (((lane >> 1) ^ (m & 7)) << 4) +
                                          (lane & 1) * 8);
                *(uint2*)(SB + AH_OFF + off) = hv;
            }
        } else {
            for (int it = 0; it < 4; it++) {
                int m = wid * 4 + it;
                int grow = row0 + m;
                float4 xv = (grow < N) ? ((const float4*)xin)[grow * 32 + lane]
                                       : make_float4(0.f, 0.f, 0.f, 0.f);
                float n2 = wredsum(xv.x * xv.x + xv.y * xv.y + xv.z * xv.z + xv.w * xv.w);
                float nrm = sqrtf(n2);
                float f = (nrm > 1e-30f) ? inv_sc2 * atanhf(sc * nrm) / nrm : 2.0f;
                uint32_t off = (uint32_t)(m * 256 + (((lane >> 1) ^ (m & 7)) << 4) +
                                          (lane & 1) * 8);
                *(uint2*)(SB + AH_OFF + off) =
                    make_uint2(pk16(f * xv.x, f * xv.y), pk16(f * xv.z, f * xv.w));
            }
        }
        __syncthreads();

        float aq[4][4], ak[4][4];
        #pragma unroll
        for (int i = 0; i < 4; i++)
            #pragma unroll
            for (int j = 0; j < 4; j++) { aq[i][j] = 0.f; ak[i][j] = 0.f; }
        gemm_pass32_qk(aq, ak, sb + AH_OFF, sb + WQ_OFF, sb + WK_OFF,
                       lane, R0, C0);
        store32_h(aq, g_qh, bq, lane, R0, C0, row0, N);
        store32_h(ak, g_kh, bk, lane, R0, C0, row0, N);

        #pragma unroll
        for (int i = 0; i < 4; i++)
            #pragma unroll
            for (int j = 0; j < 4; j++) aq[i][j] = 0.f;
        gemm_pass32(aq, sb + AH_OFF, sb + WVH_OFF, lane, R0, C0);
        store32_h(aq, g_vh, bv, lane, R0, C0, row0, N);

        __syncthreads();
    }
}

// ---------------- attention (1 node/warp, 4-edge unroll, pipelined indices) ----------------
// mode 0: write tangent h fp16 to g_th; mode 1: exp_map -> fp32 out
__global__ void __launch_bounds__(256)
edge_kernel(const float* __restrict__ curv, float* __restrict__ out, int N,
            int mode) {
    int lane = threadIdx.x & 31;
    int node = blockIdx.x * 8 + (threadIdx.x >> 5);
    if (node >= N) return;

    const uint2* qp = (const uint2*)g_qh;
    float4 qr = h4f(__ldg(&qp[node * 32 + lane]));
    int e0 = g_off[node];
    int e1 = g_off[node + 1];
    const float scale = 0.08838834764831845f;  // 1/sqrt(128)
    const uint2* kp = (const uint2*)g_kh;
    const uint2* vp = (const uint2*)g_vh;

    float z = 0.f;
    float4 acc = make_float4(0.f, 0.f, 0.f, 0.f);

    int e = e0;
    int s0, s1, s2, s3;
    if (e + 4 <= e1) {
        s0 = __ldg(&g_esrc[e]);
        s1 = __ldg(&g_esrc[e + 1]);
        s2 = __ldg(&g_esrc[e + 2]);
        s3 = __ldg(&g_esrc[e + 3]);
    }
    for (; e + 4 <= e1; e += 4) {
        uint2 ku0 = __ldg(&kp[s0 * 32 + lane]);
        uint2 ku1 = __ldg(&kp[s1 * 32 + lane]);
        uint2 ku2 = __ldg(&kp[s2 * 32 + lane]);
        uint2 ku3 = __ldg(&kp[s3 * 32 + lane]);
        uint2 vu0 = __ldg(&vp[s0 * 32 + lane]);
        uint2 vu1 = __ldg(&vp[s1 * 32 + lane]);
        uint2 vu2 = __ldg(&vp[s2 * 32 + lane]);
        uint2 vu3 = __ldg(&vp[s3 * 32 + lane]);
        // pipeline: fetch next iteration's indices before consuming gathers
        if (e + 8 <= e1) {
            s0 = __ldg(&g_esrc[e + 4]);
            s1 = __ldg(&g_esrc[e + 5]);
            s2 = __ldg(&g_esrc[e + 6]);
            s3 = __ldg(&g_esrc[e + 7]);
        }
        float4 k0 = h4f(ku0), k1 = h4f(ku1), k2 = h4f(ku2), k3 = h4f(ku3);
        float d0 = qr.x * k0.x + qr.y * k0.y + qr.z * k0.z + qr.w * k0.w;
        float d1 = qr.x * k1.x + qr.y * k1.y + qr.z * k1.z + qr.w * k1.w;
        float d2 = qr.x * k2.x + qr.y * k2.y + qr.z * k2.z + qr.w * k2.w;
        float d3 = qr.x * k3.x + qr.y * k3.y + qr.z * k3.z + qr.w * k3.w;
        #pragma unroll
        for (int o = 16; o; o >>= 1) {
            d0 += __shfl_xor_sync(0xffffffffu, d0, o);
            d1 += __shfl_xor_sync(0xffffffffu, d1, o);
            d2 += __shfl_xor_sync(0xffffffffu, d2, o);
            d3 += __shfl_xor_sync(0xffffffffu, d3, o);
        }
        float p0 = __expf(d0 * scale);
        float p1 = __expf(d1 * scale);
        float p2 = __expf(d2 * scale);
        float p3 = __expf(d3 * scale);
        z += (p0 + p1) + (p2 + p3);
        float4 v0 = h4f(vu0), v1 = h4f(vu1), v2 = h4f(vu2), v3 = h4f(vu3);
        acc.x += p0 * v0.x + p1 * v1.x + p2 * v2.x + p3 * v3.x;
        acc.y += p0 * v0.y + p1 * v1.y + p2 * v2.y + p3 * v3.y;
        acc.z += p0 * v0.z + p1 * v1.z + p2 * v2.z + p3 * v3.z;
        acc.w += p0 * v0.w + p1 * v1.w + p2 * v2.w + p3 * v3.w;
    }
    for (; e < e1; e++) {
        int s = __ldg(&g_esrc[e]);
        float4 k0 = h4f(__ldg(&kp[s * 32 + lane]));
        float4 v0 = h4f(__ldg(&vp[s * 32 + lane]));
        float d0 = qr.x * k0.x + qr.y * k0.y + qr.z * k0.z + qr.w * k0.w;
        d0 = wredsum(d0);
        float p0 = __expf(d0 * scale);
        z += p0;
        acc.x += p0 * v0.x;
        acc.y += p0 * v0.y;
        acc.z += p0 * v0.z;
        acc.w += p0 * v0.w;
    }

    float inv = 1.0f / z;
    float4 h = make_float4(acc.x * inv, acc.y * inv, acc.z * inv, acc.w * inv);

    if (mode == 0) {
        ((uint2*)g_th)[node * 32 + lane] =
            make_uint2(pk16(h.x, h.y), pk16(h.z, h.w));
        return;
    }
    float n2 = wredsum(h.x * h.x + h.y * h.y + h.z * h.z + h.w * h.w);
    float nrm = sqrtf(n2);
    float sc = sqrtf(curv[0]);
    float f = (nrm > 1e-30f) ? tanhf(0.5f * sc * nrm) / (sc * nrm) : 0.5f;
    ((float4*)out)[node * 32 + lane] =
        make_float4(f * h.x, f * h.y, f * h.z, f * h.w);
}

// ---------------- launch ----------------
extern "C" void kernel_launch(void* const* d_in, const int* in_sizes, int n_in,
                              void* d_out, int out_size) {
    const float* emb  = (const float*)d_in[0];
    const float* Wq   = (const float*)d_in[1];
    const float* bq   = (const float*)d_in[2];
    const float* Wk   = (const float*)d_in[3];
    const float* bk   = (const float*)d_in[4];
    const float* Wv   = (const float*)d_in[5];
    const float* bv   = (const float*)d_in[6];
    const float* curv = (const float*)d_in[7];
    const int*   src  = (const int*)d_in[8];
    const int*   dst  = (const int*)d_in[9];

    int N = in_sizes[0] / D;
    int E = in_sizes[8];
    int L = in_sizes[1] / (D * D);

    cudaFuncSetAttribute(qkv_gemm_hmma,
                         cudaFuncAttributeMaxDynamicSharedMemorySize, GEMM_SMEM);

    void* p;
    cudaGetSymbolAddress(&p, g_th);
    const __half* gth = (const __half*)p;
    cudaGetSymbolAddress(&p, g_cnt);
    void* gcnt_v = p;

    int nb = (N + 1023) >> 10;
    int numTiles = (N + 63) / 64;
    int nodeBlocks = (N + 7) / 8;

    cudaStream_t s2;
    cudaStreamCreateWithFlags(&s2, cudaStreamNonBlocking);
    cudaEvent_t evF, evJ;
    cudaEventCreateWithFlags(&evF, cudaEventDisableTiming);
    cudaEventCreateWithFlags(&evJ, cudaEventDisableTiming);

    cudaMemsetAsync(gcnt_v, 0, (size_t)N * sizeof(int));

    // fork: GEMM layer 0 on s2 concurrent with CSR chain on main stream
    cudaEventRecord(evF, 0);
    cudaStreamWaitEvent(s2, evF, 0);
    qkv_gemm_hmma<<<296, 512, GEMM_SMEM, s2>>>(emb, nullptr,
                                               Wq, bq, Wk, bk, Wv, bv,
                                               curv, N, numTiles);
    cudaEventRecord(evJ, s2);

    hist_kernel<<<(E + 255) / 256, 256>>>(dst, E);
    scan_local<<<nb, 256>>>(N);
    scan_tops<<<1, 128>>>(nb);
    scan_add<<<(N + 255) / 256, 256>>>(N, E);
    scatter_kernel<<<(E + 255) / 256, 256>>>(src, dst, E);

    cudaStreamWaitEvent(0, evJ, 0);

    edge_kernel<<<nodeBlocks, 256>>>(curv, (float*)d_out, N, (L == 1) ? 1 : 0);
    for (int l = 1; l < L; l++) {
        qkv_gemm_hmma<<<296, 512, GEMM_SMEM>>>(nullptr, gth,
                                               Wq + l * D * D, bq + l * D,
                                               Wk + l * D * D, bk + l * D,
                                               Wv + l * D * D, bv + l * D,
                                               curv, N, numTiles);
        edge_kernel<<<nodeBlocks, 256>>>(curv, (float*)d_out, N,
                                         (l == L - 1) ? 1 : 0);
    }

    cudaEventDestroy(evF);
    cudaEventDestroy(evJ);
    cudaStreamDestroy(s2);
}